// round 17
// baseline (speedup 1.0000x reference)
#include <cuda_runtime.h>
#include <cuda_fp16.h>
#include <cstdint>

// Problem constants
#define BB    4
#define SS    2048
#define DM    1024
#define NH    16
#define DH    64
#define TOK   (BB * SS)          // 8192 tokens

// ---------------- scratch (no cudaMalloc allowed) ----------------
__device__ __half g_qh[TOK * DM];      // [B,H,S,Dh]
__device__ __half g_kh[TOK * DM];      // [B,H,S,Dh]
__device__ __half g_vth[TOK * DM];     // [B,H,Dh,S]  (V transposed)
__device__ __half g_ah[TOK * DM];      // [B,S,D]     attn output
__device__ __half g_wh[4 * DM * DM];   // fp16 weights Wq,Wk,Wv,Wo

// ---------------- helpers ----------------
__device__ __forceinline__ uint32_t smem_u32(const void* p) {
    uint32_t a;
    asm("{ .reg .u64 t; cvta.to.shared.u64 t, %1; cvt.u32.u64 %0, t; }" : "=r"(a) : "l"(p));
    return a;
}
__device__ __forceinline__ float ex2(float x) {
    float y;
    asm("ex2.approx.ftz.f32 %0, %1;" : "=f"(y) : "f"(x));
    return y;
}
__device__ __forceinline__ void cpasync16(uint32_t dst, const void* src) {
    asm volatile("cp.async.cg.shared.global [%0], [%1], 16;" :: "r"(dst), "l"(src));
}
#define CP_COMMIT()  asm volatile("cp.async.commit_group;" ::: "memory")
#define CP_WAIT(n)   asm volatile("cp.async.wait_group " #n ";" ::: "memory")

__device__ __forceinline__ void mma16(float* c, const uint32_t* a, const uint32_t* b) {
    asm volatile(
        "mma.sync.aligned.m16n8k16.row.col.f32.f16.f16.f32 "
        "{%0,%1,%2,%3},{%4,%5,%6,%7},{%8,%9},{%0,%1,%2,%3};\n"
        : "+f"(c[0]), "+f"(c[1]), "+f"(c[2]), "+f"(c[3])
        : "r"(a[0]), "r"(a[1]), "r"(a[2]), "r"(a[3]),
          "r"(b[0]), "r"(b[1]));
}
__device__ __forceinline__ uint32_t h2u(__half2 h) {
    return *reinterpret_cast<uint32_t*>(&h);
}
#define LDSM4(r0, r1, r2, r3, addr)                                            \
    asm volatile("ldmatrix.sync.aligned.m8n8.x4.shared.b16 {%0,%1,%2,%3}, [%4];" \
                 : "=r"(r0), "=r"(r1), "=r"(r2), "=r"(r3) : "r"(addr))
#define STS64(addr, lo, hi) \
    asm volatile("st.shared.v2.b32 [%0], {%1,%2};" :: "r"(addr), "r"(lo), "r"(hi))

// ---------------- fp32 -> fp16 weight conversion (inputs converted in-GEMM) ----
#define N4W (DM * DM / 4)

__global__ void cvt_w(const float* __restrict__ Wq, const float* __restrict__ Wk,
                      const float* __restrict__ Wv, const float* __restrict__ Wo)
{
    int i = blockIdx.x * blockDim.x + threadIdx.x;
    int seg = i / N4W;
    int off = i - seg * N4W;
    const float4* s = (const float4*)(seg == 0 ? Wq : seg == 1 ? Wk : seg == 2 ? Wv : Wo);
    __half2* d = (__half2*)(g_wh + (size_t)seg * DM * DM);
    float4 v = s[off];
    d[2 * off]     = __floats2half2_rn(v.x, v.y);
    d[2 * off + 1] = __floats2half2_rn(v.z, v.w);
}

// ---------------- fp16 GEMM (mma m16n8k16 + ldmatrix, K-step 64) ----------------
// C[8192,1024] = A[8192,1024(K-major)] @ W[1024,1024(K-major)]^T + bias
// A-fragment double-buffering ONLY (+16 regs vs round 15): the next s-step's
// 4 A-LDSMs issue before the current step's MMAs; B frags load fresh (2 LDSM,
// latency covered by the previous step's tensor-pipe drain).
// Rows: 64 halves = 128B data, pitch 144B (conflict-free ldmatrix phases).
// CVTA=true: A read as raw fp32, cvt in-register (two 4xfloat4 batches/iter,
// same placement as round 15).
#define GP2   144
#define GAB   (128 * GP2)        // 18432 per operand
#define GSTG  (2 * GAB)          // 36864 per stage (A then B)
#define GSMEM (3 * GSTG)         // 110592  (x2 CTAs = 221184 <= 233KB)

struct GArgs {
    const float*  Af[3];   // fp32 A (CVTA=true)
    const __half* A[3];    // fp16 A (CVTA=false)
    const __half* W[3];
    const float*  bias[3];
    void*         out[3];
    int mode;
};

template <bool CVTA>
__global__ void __launch_bounds__(256, 2)
gemm_h(GArgs ga)
{
    extern __shared__ char smc[];
    const uint32_t sb = smem_u32(smc);
    const int z = blockIdx.z;
    const float* __restrict__ Af   = ga.Af[z];
    const __half* __restrict__ A   = ga.A[z];
    const __half* __restrict__ W   = ga.W[z];
    const float* __restrict__ bias = ga.bias[z];
    const int mode = ga.mode;

    const int tid  = threadIdx.x;
    const int warp = tid >> 5, lane = tid & 31;
    const int g = lane >> 2, t = lane & 3;
    const int wm = warp >> 2, wn = warp & 3;
    const int bm = blockIdx.y * 128, bn = blockIdx.x * 128;
    const int lrow = lane & 7, sel = lane >> 3;

    const uint32_t offA = (uint32_t)(lrow * GP2 + (sel & 1) * (8 * GP2) + (sel >> 1) * 16);
    const uint32_t offB = (uint32_t)(lrow * GP2 + (sel & 1) * 16 + (sel >> 1) * (8 * GP2));

    const float*  Ab32 = Af + (size_t)bm * DM;
    const __half* Ab   = A + (size_t)bm * DM;
    const __half* Wb   = W + (size_t)bn * DM;

    float acc[4][4][4];
#pragma unroll
    for (int i = 0; i < 4; i++)
#pragma unroll
        for (int j = 0; j < 4; j++)
#pragma unroll
            for (int e = 0; e < 4; e++) acc[i][j][e] = 0.f;

    // B tile: 128 rows x 64 halves (128B data/row), 4 cp.async per thread
#define LOAD_B(kt, stg)                                                         \
    do {                                                                        \
        uint32_t bB = sb + (stg) * GSTG + GAB;                                  \
        int kc = (kt) * 64;                                                     \
        _Pragma("unroll")                                                       \
        for (int i_ = 0; i_ < 4; i_++) {                                        \
            int id = tid + i_ * 256;                                            \
            int r_ = id >> 3, c_ = id & 7;                                      \
            cpasync16(bB + r_ * GP2 + c_ * 16, Wb + (size_t)r_ * DM + kc + c_ * 8); \
        }                                                                       \
    } while (0)

#define LOAD_A16(kt, stg)                                                       \
    do {                                                                        \
        uint32_t bA = sb + (stg) * GSTG;                                        \
        int kc = (kt) * 64;                                                     \
        _Pragma("unroll")                                                       \
        for (int i_ = 0; i_ < 4; i_++) {                                        \
            int id = tid + i_ * 256;                                            \
            int r_ = id >> 3, c_ = id & 7;                                      \
            cpasync16(bA + r_ * GP2 + c_ * 16, Ab + (size_t)r_ * DM + kc + c_ * 8); \
        }                                                                       \
    } while (0)

    // fp32 A batch LDG / STS (batch bt in {0,1}: 4 float4 per thread) — round-15 form
#define LDG_A32(kt, bt, pre)                                                    \
    do {                                                                        \
        int kc = (kt) * 64;                                                     \
        _Pragma("unroll")                                                       \
        for (int i_ = 0; i_ < 4; i_++) {                                        \
            int id = tid + ((bt) * 4 + i_) * 256;                               \
            int r_ = id >> 4, c4 = id & 15;                                     \
            (pre)[i_] = *(const float4*)(Ab32 + (size_t)r_ * DM + kc + c4 * 4); \
        }                                                                       \
    } while (0)

#define STS_A32(stg, bt, pre)                                                   \
    do {                                                                        \
        uint32_t bA = sb + (stg) * GSTG;                                        \
        _Pragma("unroll")                                                       \
        for (int i_ = 0; i_ < 4; i_++) {                                        \
            int id = tid + ((bt) * 4 + i_) * 256;                               \
            int r_ = id >> 4, c4 = id & 15;                                     \
            STS64(bA + r_ * GP2 + c4 * 8,                                       \
                  h2u(__floats2half2_rn((pre)[i_].x, (pre)[i_].y)),             \
                  h2u(__floats2half2_rn((pre)[i_].z, (pre)[i_].w)));            \
        }                                                                       \
    } while (0)

    // prologue: tiles 0,1 (round-15 form)
    if (CVTA) {
        float4 p0[4];
#pragma unroll
        for (int pt = 0; pt < 2; pt++) {
            LDG_A32(pt, 0, p0); STS_A32(pt, 0, p0);
            LDG_A32(pt, 1, p0); STS_A32(pt, 1, p0);
        }
        LOAD_B(0, 0); CP_COMMIT();
        LOAD_B(1, 1); CP_COMMIT();
    } else {
        LOAD_A16(0, 0); LOAD_B(0, 0); CP_COMMIT();
        LOAD_A16(1, 1); LOAD_B(1, 1); CP_COMMIT();
    }

    for (int tt = 0; tt < 16; tt++) {
        if (tt < 15) { CP_WAIT(1); } else { CP_WAIT(0); }
        __syncthreads();

        const bool pref = (tt + 2 < 16);
        const int stg2 = (tt + 2) % 3;
        float4 pre[4];
        if (pref) {
            if (CVTA) {
                LDG_A32(tt + 2, 0, pre);   // batch0 in flight over s=0,1
                LOAD_B(tt + 2, stg2);
            } else {
                LOAD_A16(tt + 2, stg2);
                LOAD_B(tt + 2, stg2);
            }
        }

        const uint32_t sAu = sb + (tt % 3) * GSTG;
        const uint32_t sBu = sAu + GAB;

        // A-frag double buffer: afb[s&1] holds step s fragments
        uint32_t afb[2][4][4];

#define LDA(buf, s)                                                             \
        do {                                                                    \
            _Pragma("unroll")                                                   \
            for (int i = 0; i < 4; i++)                                         \
                LDSM4(afb[buf][i][0], afb[buf][i][1], afb[buf][i][2], afb[buf][i][3], \
                      sAu + (uint32_t)((wm * 64 + i * 16) * GP2 + (s) * 32) + offA); \
        } while (0)

#define STEP(s)                                                                 \
        do {                                                                    \
            uint32_t bft[4][2];                                                 \
            _Pragma("unroll")                                                   \
            for (int j2 = 0; j2 < 2; j2++)                                      \
                LDSM4(bft[2 * j2][0], bft[2 * j2][1],                           \
                      bft[2 * j2 + 1][0], bft[2 * j2 + 1][1],                   \
                      sBu + (uint32_t)((wn * 32 + j2 * 16) * GP2 + (s) * 32) + offB); \
            if ((s) < 3) LDA(((s) + 1) & 1, (s) + 1);                           \
            _Pragma("unroll")                                                   \
            for (int i = 0; i < 4; i++)                                         \
                _Pragma("unroll")                                               \
                for (int j = 0; j < 4; j++) mma16(acc[i][j], afb[(s) & 1][i], bft[j]); \
        } while (0)

        LDA(0, 0);
        STEP(0);
        STEP(1);
        if (CVTA && pref) { STS_A32(stg2, 0, pre); LDG_A32(tt + 2, 1, pre); }
        STEP(2);
        STEP(3);
        if (CVTA && pref) STS_A32(stg2, 1, pre);
        if (pref) CP_COMMIT();
#undef LDA
#undef STEP
    }
#undef LOAD_B
#undef LOAD_A16
#undef LDG_A32
#undef STS_A32

    // epilogue
#pragma unroll
    for (int i = 0; i < 4; i++) {
#pragma unroll
        for (int j = 0; j < 4; j++) {
            int row0 = bm + wm * 64 + i * 16 + g;
            int col0 = bn + wn * 32 + j * 8 + 2 * t;
            float b0 = bias[col0], b1 = bias[col0 + 1];
            float c00 = acc[i][j][0] + b0, c01 = acc[i][j][1] + b1;
            float c10 = acc[i][j][2] + b0, c11 = acc[i][j][3] + b1;
            if (mode == 1) {
                float* out = (float*)ga.out[z];
                out[(size_t)row0 * DM + col0]           = c00;
                out[(size_t)row0 * DM + col0 + 1]       = c01;
                out[(size_t)(row0 + 8) * DM + col0]     = c10;
                out[(size_t)(row0 + 8) * DM + col0 + 1] = c11;
            } else {
                __half* out = (__half*)ga.out[z];
                int h = col0 >> 6, dh0 = col0 & 63;
                int b = row0 >> 11, s = row0 & 2047;
                if (z < 2) {
                    size_t base = (((size_t)(b * NH + h) * SS) + s) * DH + dh0;
                    *(__half2*)(out + base)          = __floats2half2_rn(c00, c01);
                    *(__half2*)(out + base + 8 * DH) = __floats2half2_rn(c10, c11);
                } else {
                    size_t base = ((size_t)(b * NH + h) * DH + dh0) * SS + s;
                    out[base]          = __float2half_rn(c00);
                    out[base + SS]     = __float2half_rn(c01);
                    out[base + 8]      = __float2half_rn(c10);
                    out[base + SS + 8] = __float2half_rn(c11);
                }
            }
        }
    }
}

// ---------------- Flash attention (fp16 mma + ldmatrix, Q in smem, occ 2) --------
// UNCHANGED from round 15 (passing, 482us config).
#define KPIT   144
#define VPIT   272
#define QPIT   144
#define KBYTES (128 * KPIT)          // 18432
#define VBYTES (64 * VPIT)           // 17408
#define BUFB   (KBYTES + VBYTES)     // 35840
#define QOFF   (2 * BUFB)            // 71680
#define ASMEM  (QOFF + 128 * QPIT)   // 90112  (x2 CTAs = 180224 <= 227KB)

__global__ void __launch_bounds__(256, 2)
attn_h(const __half* __restrict__ q, const __half* __restrict__ k,
       const __half* __restrict__ vt, __half* __restrict__ out)
{
    extern __shared__ char smc[];
    const uint32_t sba = smem_u32(smc);

    const int tid = threadIdx.x, warp = tid >> 5, lane = tid & 31;
    const int g = lane >> 2, t = lane & 3;
    const int bh = blockIdx.y, qt = blockIdx.x;
    const int band = warp * 16;
    const int lrow = lane & 7, sel = lane >> 3;

    const uint32_t offK = (uint32_t)(lrow * KPIT + (sel & 1) * 16 + (sel >> 1) * (8 * KPIT));
    const uint32_t offV = (uint32_t)(lrow * VPIT + (sel & 1) * 16 + (sel >> 1) * (8 * VPIT));
    const uint32_t offQ = (uint32_t)(lrow * QPIT + (sel & 1) * (8 * QPIT) + (sel >> 1) * 16);

    const __half* qb  = q  + (size_t)bh * SS * DH;
    const __half* kb  = k  + (size_t)bh * SS * DH;
    const __half* vtb = vt + (size_t)bh * DH * SS;

#define AFILL(tile, buf)                                                            \
    do {                                                                            \
        uint32_t kb_ = sba + (buf) * BUFB;                                          \
        uint32_t vb_ = kb_ + KBYTES;                                                \
        _Pragma("unroll")                                                           \
        for (int i_ = 0; i_ < 4; i_++) {                                            \
            int id = tid + i_ * 256;                                                \
            int rk = id >> 3, ck = id & 7;                                          \
            cpasync16(kb_ + rk * KPIT + ck * 16,                                    \
                      kb + (size_t)((tile) * 128 + rk) * DH + ck * 8);              \
            int rv = id >> 4, cv = id & 15;                                         \
            cpasync16(vb_ + rv * VPIT + cv * 16,                                    \
                      vtb + (size_t)rv * SS + (tile) * 128 + cv * 8);               \
        }                                                                           \
    } while (0)

    // Q tile -> smem (raw fp16 copy; softmax scale applied post-MMA on sf)
    {
        uint32_t qs = sba + QOFF;
#pragma unroll
        for (int i_ = 0; i_ < 4; i_++) {
            int id = tid + i_ * 256;
            int rq = id >> 3, cq = id & 7;
            cpasync16(qs + rq * QPIT + cq * 16,
                      qb + (size_t)(qt * 128 + rq) * DH + cq * 8);
        }
    }
    AFILL(0, 0); CP_COMMIT();

    const float SCL = 0.125f * 1.4426950408889634f;  // 1/sqrt(64) * log2(e)
    const uint32_t qrow = sba + QOFF + (uint32_t)(band * QPIT);

    float m0 = -INFINITY, m1 = -INFINITY, l0 = 0.f, l1 = 0.f;
    float oa[8][4];
#pragma unroll
    for (int j = 0; j < 8; j++)
#pragma unroll
        for (int e = 0; e < 4; e++) oa[j][e] = 0.f;

    for (int kv = 0; kv < 16; kv++) {
        CP_WAIT(0);
        __syncthreads();
        if (kv < 15) { AFILL(kv + 1, (kv + 1) & 1); CP_COMMIT(); }

        const uint32_t Ksu = sba + (kv & 1) * BUFB;
        const uint32_t Vtu = Ksu + KBYTES;

        // S = Q * K^T
        float sf[16][4];
#pragma unroll
        for (int j = 0; j < 16; j++)
#pragma unroll
            for (int e = 0; e < 4; e++) sf[j][e] = 0.f;
#pragma unroll
        for (int s = 0; s < 4; s++) {
            uint32_t qa[4];
            LDSM4(qa[0], qa[1], qa[2], qa[3], qrow + (uint32_t)(s * 32) + offQ);
#pragma unroll
            for (int j2 = 0; j2 < 8; j2++) {
                uint32_t b0[2], b1[2];
                LDSM4(b0[0], b0[1], b1[0], b1[1],
                      Ksu + (uint32_t)(j2 * 16 * KPIT + s * 32) + offK);
                mma16(sf[2 * j2],     qa, b0);
                mma16(sf[2 * j2 + 1], qa, b1);
            }
        }
        // softmax scale (log2 domain)
#pragma unroll
        for (int j = 0; j < 16; j++)
#pragma unroll
            for (int e = 0; e < 4; e++) sf[j][e] *= SCL;

        // online softmax
        float mt0 = -INFINITY, mt1 = -INFINITY;
#pragma unroll
        for (int j = 0; j < 16; j++) {
            mt0 = fmaxf(mt0, fmaxf(sf[j][0], sf[j][1]));
            mt1 = fmaxf(mt1, fmaxf(sf[j][2], sf[j][3]));
        }
        mt0 = fmaxf(mt0, __shfl_xor_sync(0xffffffffu, mt0, 1));
        mt0 = fmaxf(mt0, __shfl_xor_sync(0xffffffffu, mt0, 2));
        mt1 = fmaxf(mt1, __shfl_xor_sync(0xffffffffu, mt1, 1));
        mt1 = fmaxf(mt1, __shfl_xor_sync(0xffffffffu, mt1, 2));

        float mn0 = fmaxf(m0, mt0), mn1 = fmaxf(m1, mt1);
        float al0 = ex2(m0 - mn0), al1 = ex2(m1 - mn1);

        // P stays in registers: C-frag(S) layout == A-frag(PV) layout
        uint32_t pf[16][2];
        float rs0 = 0.f, rs1 = 0.f;
#pragma unroll
        for (int j = 0; j < 16; j++) {
            float p0 = ex2(sf[j][0] - mn0);
            float p1 = ex2(sf[j][1] - mn0);
            float p2 = ex2(sf[j][2] - mn1);
            float p3 = ex2(sf[j][3] - mn1);
            rs0 += p0 + p1;
            rs1 += p2 + p3;
            pf[j][0] = h2u(__floats2half2_rn(p0, p1));   // row g
            pf[j][1] = h2u(__floats2half2_rn(p2, p3));   // row g+8
        }
        rs0 += __shfl_xor_sync(0xffffffffu, rs0, 1);
        rs0 += __shfl_xor_sync(0xffffffffu, rs0, 2);
        rs1 += __shfl_xor_sync(0xffffffffu, rs1, 1);
        rs1 += __shfl_xor_sync(0xffffffffu, rs1, 2);

        l0 = l0 * al0 + rs0;
        l1 = l1 * al1 + rs1;
        m0 = mn0;
        m1 = mn1;
#pragma unroll
        for (int j = 0; j < 8; j++) {
            oa[j][0] *= al0; oa[j][1] *= al0;
            oa[j][2] *= al1; oa[j][3] *= al1;
        }

        // O += P * V  (P from registers, V via ldmatrix)
#pragma unroll
        for (int kk = 0; kk < 8; kk++) {
            uint32_t af[4];
            af[0] = pf[2 * kk][0];
            af[1] = pf[2 * kk][1];
            af[2] = pf[2 * kk + 1][0];
            af[3] = pf[2 * kk + 1][1];
#pragma unroll
            for (int j2 = 0; j2 < 4; j2++) {
                uint32_t b0[2], b1[2];
                LDSM4(b0[0], b0[1], b1[0], b1[1],
                      Vtu + (uint32_t)(j2 * 16 * VPIT + kk * 32) + offV);
                mma16(oa[2 * j2],     af, b0);
                mma16(oa[2 * j2 + 1], af, b1);
            }
        }
        // next iteration's top __syncthreads covers buffer reuse
    }
#undef AFILL

    float i0 = 1.f / l0, i1 = 1.f / l1;
    int b = bh >> 4, h = bh & 15;
    int tr0 = b * SS + qt * 128 + band + g;
    __half* ob0 = out + (size_t)tr0 * DM + h * DH;
    __half* ob1 = out + (size_t)(tr0 + 8) * DM + h * DH;
#pragma unroll
    for (int j = 0; j < 8; j++) {
        int c = j * 8 + 2 * t;
        *(__half2*)(ob0 + c) = __floats2half2_rn(oa[j][0] * i0, oa[j][1] * i0);
        *(__half2*)(ob1 + c) = __floats2half2_rn(oa[j][2] * i1, oa[j][3] * i1);
    }
}

// ---------------- launcher ----------------
extern "C" void kernel_launch(void* const* d_in, const int* in_sizes, int n_in,
                              void* d_out, int out_size)
{
    const float* Q  = (const float*)d_in[0];
    const float* K  = (const float*)d_in[1];
    const float* V  = (const float*)d_in[2];
    const float* Wq = (const float*)d_in[3];
    const float* bq = (const float*)d_in[4];
    const float* Wk = (const float*)d_in[5];
    const float* bk = (const float*)d_in[6];
    const float* Wv = (const float*)d_in[7];
    const float* bv = (const float*)d_in[8];
    const float* Wo = (const float*)d_in[9];
    const float* bo = (const float*)d_in[10];

    __half *qh, *kh, *vth, *ah, *wh;
    cudaGetSymbolAddress((void**)&qh,  g_qh);
    cudaGetSymbolAddress((void**)&kh,  g_kh);
    cudaGetSymbolAddress((void**)&vth, g_vth);
    cudaGetSymbolAddress((void**)&ah,  g_ah);
    cudaGetSymbolAddress((void**)&wh,  g_wh);

    cudaFuncSetAttribute(attn_h, cudaFuncAttributeMaxDynamicSharedMemorySize, ASMEM);
    cudaFuncSetAttribute(gemm_h<true>,  cudaFuncAttributeMaxDynamicSharedMemorySize, GSMEM);
    cudaFuncSetAttribute(gemm_h<false>, cudaFuncAttributeMaxDynamicSharedMemorySize, GSMEM);

    // fp32 -> fp16 weights only (inputs converted inside the QKV GEMM)
    cvt_w<<<4 * N4W / 256, 256>>>(Wq, Wk, Wv, Wo);

    // merged Q/K/V projection GEMMs: raw fp32 A, in-kernel conversion
    GArgs gp;
    gp.Af[0] = Q;    gp.Af[1] = K;    gp.Af[2] = V;
    gp.A[0] = nullptr; gp.A[1] = nullptr; gp.A[2] = nullptr;
    gp.W[0] = wh;    gp.W[1] = wh + DM * DM; gp.W[2] = wh + 2 * DM * DM;
    gp.bias[0] = bq; gp.bias[1] = bk;        gp.bias[2] = bv;
    gp.out[0] = qh;  gp.out[1] = kh;         gp.out[2] = vth;
    gp.mode = 0;
    dim3 ggrid(DM / 128, TOK / 128, 3);   // (8, 64, 3)
    gemm_h<true><<<ggrid, 256, GSMEM>>>(gp);

    dim3 agrid(SS / 128, BB * NH);        // (16, 64)
    attn_h<<<agrid, 256, ASMEM>>>(qh, kh, vth, ah);

    // output projection (fp16 A from attn, fp32 result)
    GArgs go;
    go.Af[0] = nullptr; go.Af[1] = nullptr; go.Af[2] = nullptr;
    go.A[0] = ah;  go.A[1] = ah;  go.A[2] = ah;
    go.W[0] = wh + 3 * DM * DM; go.W[1] = go.W[0]; go.W[2] = go.W[0];
    go.bias[0] = bo; go.bias[1] = bo; go.bias[2] = bo;
    go.out[0] = d_out; go.out[1] = d_out; go.out[2] = d_out;
    go.mode = 1;
    dim3 ogrid(DM / 128, TOK / 128, 1);
    gemm_h<false><<<ogrid, 256, GSMEM>>>(go);
}